// round 14
// baseline (speedup 1.0000x reference)
#include <cuda_runtime.h>
#include <math.h>

#define N_TOK 4096
#define D_DIM 2048
#define TK    1024
#define NSEL  256         // persistent selection CTAs (2 per SM), 16 tokens each
#define TPB   16          // tokens per CTA
#define NTHR  512         // 16 warps: 1 token per warp
#define EPSV  1e-6f

// ---------------- device global scratch (no allocations allowed) ----------------
__device__ float g_F[N_TOK][D_DIM];      // normalized features (32 MB)
__device__ float g_K[N_TOK][N_TOK];      // r_n * sim * r_m     (64 MB)
__device__ float g_C[N_TOK][TK];         // cis, token-major: g_C[m][t] = cis[t][m]
__device__ float g_r[N_TOK];
__device__ float g_di2s[N_TOK];
__device__ float g_mn, g_mx;

struct __align__(16) StepSlot {
    unsigned long long slot;   // packed (value, idx) winner key
    unsigned int done;         // CTA completion count
    unsigned int pad;
};
__device__ StepSlot g_step[TK + 2];

// ---------------- init: reset per-replay state ------------------------------------
__global__ void init_ker() {
    int t = blockIdx.x * blockDim.x + threadIdx.x;
    if (t < TK + 2) { g_step[t].slot = 0ull; g_step[t].done = 0u; g_step[t].pad = 0u; }
}

// ---------------- min/max of relevance = -attn -------------------------------------
__global__ void minmax_ker(const float* __restrict__ attn) {
    __shared__ float smn[256], smx[256];
    int tid = threadIdx.x;
    float mn = INFINITY, mx = -INFINITY;
    for (int i = tid; i < N_TOK; i += 256) {
        float v = -attn[i];
        mn = fminf(mn, v); mx = fmaxf(mx, v);
    }
    smn[tid] = mn; smx[tid] = mx; __syncthreads();
    for (int s = 128; s > 0; s >>= 1) {
        if (tid < s) {
            smn[tid] = fminf(smn[tid], smn[tid + s]);
            smx[tid] = fmaxf(smx[tid], smx[tid + s]);
        }
        __syncthreads();
    }
    if (tid == 0) { g_mn = smn[0]; g_mx = smx[0]; }
}

__global__ void relev_ker(const float* __restrict__ attn) {
    int n = blockIdx.x * blockDim.x + threadIdx.x;
    if (n < N_TOK) {
        g_r[n] = ((-attn[n]) - g_mn + EPSV) / (g_mx - g_mn);
    }
}

// ---------------- row L2-normalize --------------------------------------------------
__global__ void norm_ker(const float* __restrict__ X) {
    int row = blockIdx.x;
    int tid = threadIdx.x;
    const float4* x4 = (const float4*)(X + (size_t)row * D_DIM);
    float4 v0 = x4[tid], v1 = x4[tid + 256];
    float ss = v0.x*v0.x + v0.y*v0.y + v0.z*v0.z + v0.w*v0.w
             + v1.x*v1.x + v1.y*v1.y + v1.z*v1.z + v1.w*v1.w;
    __shared__ float sred[256];
    sred[tid] = ss; __syncthreads();
    for (int s = 128; s > 0; s >>= 1) {
        if (tid < s) sred[tid] += sred[tid + s];
        __syncthreads();
    }
    float inv = 1.0f / sqrtf(sred[0]);
    v0.x *= inv; v0.y *= inv; v0.z *= inv; v0.w *= inv;
    v1.x *= inv; v1.y *= inv; v1.z *= inv; v1.w *= inv;
    float4* o4 = (float4*)(&g_F[row][0]);
    o4[tid] = v0; o4[tid + 256] = v1;
}

// ---------------- packed f32x2 FMA helpers -----------------------------------------
__device__ __forceinline__ void fma2(unsigned long long& d,
                                     unsigned long long a, unsigned long long b) {
    asm("fma.rn.f32x2 %0, %1, %2, %3;" : "=l"(d) : "l"(a), "l"(b), "l"(d));
}
__device__ __forceinline__ unsigned long long bcast2(float x) {
    unsigned long long d;
    unsigned r = __float_as_uint(x);
    asm("mov.b64 %0, {%1, %1};" : "=l"(d) : "r"(r));
    return d;
}

// ---------------- K = diag(r) * F F^T * diag(r), symmetric half --------------------
__global__ void __launch_bounds__(256) gemm_ker() {
    int bx = blockIdx.x, by = blockIdx.y;
    if (by > bx) return;                 // lower-triangular tiles only
    __shared__ float As[16][132];
    __shared__ float Bs[16][132];
    int tid = threadIdx.x;
    int tx = tid & 15, ty = tid >> 4;
    int lr = tid >> 2;                   // 0..63
    int lc = (tid & 3) * 4;              // 0,4,8,12
    const float* Ab = &g_F[bx * 128 + lr][lc];
    const float* Bb = &g_F[by * 128 + lr][lc];
    unsigned long long acc2[8][4];       // 8 rows x 4 packed col-pairs
    #pragma unroll
    for (int i = 0; i < 8; i++)
        #pragma unroll
        for (int p = 0; p < 4; p++) acc2[i][p] = 0ull;  // (0.0f, 0.0f)

    for (int k0 = 0; k0 < D_DIM; k0 += 16) {
        float4 a0 = *(const float4*)(Ab + k0);
        float4 a1 = *(const float4*)(Ab + (size_t)64 * D_DIM + k0);
        float4 b0 = *(const float4*)(Bb + k0);
        float4 b1 = *(const float4*)(Bb + (size_t)64 * D_DIM + k0);
        As[lc + 0][lr] = a0.x; As[lc + 1][lr] = a0.y; As[lc + 2][lr] = a0.z; As[lc + 3][lr] = a0.w;
        As[lc + 0][lr + 64] = a1.x; As[lc + 1][lr + 64] = a1.y; As[lc + 2][lr + 64] = a1.z; As[lc + 3][lr + 64] = a1.w;
        Bs[lc + 0][lr] = b0.x; Bs[lc + 1][lr] = b0.y; Bs[lc + 2][lr] = b0.z; Bs[lc + 3][lr] = b0.w;
        Bs[lc + 0][lr + 64] = b1.x; Bs[lc + 1][lr + 64] = b1.y; Bs[lc + 2][lr + 64] = b1.z; Bs[lc + 3][lr + 64] = b1.w;
        __syncthreads();
        #pragma unroll
        for (int kk = 0; kk < 16; kk++) {
            float4 ra0 = *(float4*)&As[kk][ty * 8];
            float4 ra1 = *(float4*)&As[kk][ty * 8 + 4];
            const unsigned long long* bp = (const unsigned long long*)&Bs[kk][tx * 8];
            unsigned long long bb[4] = {bp[0], bp[1], bp[2], bp[3]};
            float a[8] = {ra0.x, ra0.y, ra0.z, ra0.w, ra1.x, ra1.y, ra1.z, ra1.w};
            #pragma unroll
            for (int i = 0; i < 8; i++) {
                unsigned long long aa = bcast2(a[i]);
                #pragma unroll
                for (int p = 0; p < 4; p++) fma2(acc2[i][p], aa, bb[p]);
            }
        }
        __syncthreads();
    }

    int r0 = bx * 128 + ty * 8;
    int c0 = by * 128 + tx * 8;
    float rr[8], rc[8];
    #pragma unroll
    for (int i = 0; i < 8; i++) rr[i] = g_r[r0 + i];
    #pragma unroll
    for (int j = 0; j < 8; j++) rc[j] = g_r[c0 + j];
    #pragma unroll
    for (int i = 0; i < 8; i++) {
        float av[8];
        #pragma unroll
        for (int p = 0; p < 4; p++) {
            unsigned lo, hi;
            asm("mov.b64 {%0, %1}, %2;" : "=r"(lo), "=r"(hi) : "l"(acc2[i][p]));
            av[2 * p]     = __uint_as_float(lo);
            av[2 * p + 1] = __uint_as_float(hi);
        }
        #pragma unroll
        for (int j = 0; j < 8; j++) {
            float v = av[j] * rr[i] * rc[j];
            g_K[r0 + i][c0 + j] = v;
            if (bx != by) g_K[c0 + j][r0 + i] = v;
        }
    }
}

__global__ void diag_ker() {
    int n = blockIdx.x * 256 + threadIdx.x;
    if (n < N_TOK) g_di2s[n] = g_K[n][n];
}

// ---------------- key packing: order-preserving float + first-index tiebreak -------
__device__ __forceinline__ unsigned long long packkey(float f, int idx) {
    unsigned u = __float_as_uint(f);
    u = (u & 0x80000000u) ? ~u : (u | 0x80000000u);
    return ((unsigned long long)u << 32) | (unsigned)(0xFFFFFFFFu - (unsigned)idx);
}

// ---------------- initial argmax over di2s -----------------------------------------
__global__ void argmax0_ker() {
    int n = blockIdx.x * 1024 + threadIdx.x;
    int lane = threadIdx.x & 31;
    unsigned long long k = (n < N_TOK) ? packkey(g_di2s[n], n) : 0ull;
    #pragma unroll
    for (int o = 16; o; o >>= 1) {
        unsigned long long t = __shfl_xor_sync(0xffffffffu, k, o);
        if (t > k) k = t;
    }
    if (lane == 0 && k) atomicMax(&g_step[0].slot, k);
}

// ---------------- persistent greedy DPP selection ----------------------------------
// 256 CTAs x 512 threads (2 CTAs/SM); CTA b owns tokens b*16..b*16+15;
// warp w owns token w (1 token per warp). R13 protocol otherwise.
__global__ void __launch_bounds__(NTHR, 2) select_ker(float* __restrict__ out, int topk) {
    extern __shared__ float sh[];
    float* C_sh  = sh;                    // [TPB][TK] = 64 KB, own C rows
    float* cj_sh = sh + TPB * TK;         // [TK]      = 4 KB
    __shared__ float kj_sh[TPB];
    __shared__ float di_sh[TPB];
    __shared__ unsigned long long warpmax[TPB];
    __shared__ unsigned long long s_key;

    int tid = threadIdx.x, lane = tid & 31, wid = tid >> 5;   // wid 0..15 = token
    int m0 = (int)blockIdx.x * TPB;
    int m  = m0 + wid;                    // this warp's token

    if (tid < TPB) di_sh[tid] = g_di2s[m0 + tid];
    __syncthreads();

    for (int i = 0; i < topk; i++) {
        // ---- wait for step-i winner; fused poll reads done+slot in one 16B load ----
        if (tid == 0) {
            if (i == 0) {
                s_key = *(volatile unsigned long long*)&g_step[0].slot;  // prior kernel
            } else {
                unsigned w0, w1, w2, w3;
                for (;;) {
                    asm volatile("ld.volatile.global.v4.u32 {%0,%1,%2,%3}, [%4];"
                                 : "=r"(w0), "=r"(w1), "=r"(w2), "=r"(w3)
                                 : "l"(&g_step[i]));
                    if (w2 >= (unsigned)NSEL) break;      // done counter
                }
                __threadfence();
                s_key = ((unsigned long long)w1 << 32) | w0;  // little-endian slot
            }
        }
        __syncthreads();

        unsigned long long key = s_key;
        int j = (int)(0xFFFFFFFFu - (unsigned)(key & 0xFFFFFFFFull));
        unsigned uv = (unsigned)(key >> 32);
        uv = (uv & 0x80000000u) ? (uv ^ 0x80000000u) : ~uv;
        float sd = sqrtf(__uint_as_float(uv));

        if (blockIdx.x == 0 && tid == 0) out[i] = (float)j;   // float32 output

        // ---- concurrent: warp0 prefetches K[j] slice; warps 1-15 stage C[j][0..i) --
        int i4 = i >> 2;
        if (wid == 0) {
            if (lane < TPB) kj_sh[lane] = __ldcg(&g_K[j][m0 + lane]);
        } else {
            int st = tid - 32;                         // 0..479
            const float4* gcj4 = (const float4*)&g_C[j][0];
            for (int t = st; t < i4; t += NTHR - 32)
                ((float4*)cj_sh)[t] = __ldcg(&gcj4[t]);
            for (int t = (i4 << 2) + st; t < i; t += NTHR - 32)
                cj_sh[t] = __ldcg(&g_C[j][t]);
        }
        __syncthreads();

        // ---- one token per warp: dot over staged cj ----
        float dcur = di_sh[wid];
        unsigned long long best = 0ull;
        if (dcur != -INFINITY) {                       // dead token: whole warp skips
            const float4* cj4 = (const float4*)cj_sh;
            const float4* cm4 = (const float4*)(C_sh + wid * TK);
            float cdot = 0.f;
            for (int t = lane; t < i4; t += 32) {
                float4 a = cj4[t], b = cm4[t];
                cdot += a.x * b.x + a.y * b.y + a.z * b.z + a.w * b.w;
            }
            for (int t = (i4 << 2) + lane; t < i; t += 32)
                cdot += cj_sh[t] * C_sh[wid * TK + t];
            #pragma unroll
            for (int o = 16; o; o >>= 1)
                cdot += __shfl_xor_sync(0xffffffffu, cdot, o);
            if (lane == 0) {
                float eis = (kj_sh[wid] - cdot) / sd;
                C_sh[wid * TK + i] = eis;              // smem copy (own dots)
                g_C[m][i] = eis;                       // publish for other CTAs
                float d = dcur - eis * eis;
                if (m == j) d = -INFINITY;
                di_sh[wid] = d;
                if (d != -INFINITY) best = packkey(d, m);
            }
        }

        if (i + 1 < topk) {
            if (lane == 0) warpmax[wid] = best;
            __syncthreads();
            if (wid == 0) {
                unsigned long long k = (lane < TPB) ? warpmax[lane] : 0ull;
                #pragma unroll
                for (int o = 8; o; o >>= 1) {
                    unsigned long long t = __shfl_xor_sync(0xffffffffu, k, o);
                    if (t > k) k = t;
                }
                if (lane == 0 && k) atomicMax(&g_step[i + 1].slot, k);
            }
            // ---- publish: make C writes + slot contribution visible, then signal ----
            __threadfence();
            __syncthreads();
            if (tid == 0) atomicAdd(&g_step[i + 1].done, 1u);
        }
    }
}

// ---------------- host entry --------------------------------------------------------
extern "C" void kernel_launch(void* const* d_in, const int* in_sizes, int n_in,
                              void* d_out, int out_size) {
    // Robust input selection by element count
    const float* feat = (const float*)d_in[0];
    const float* attn = (const float*)d_in[1];
    for (int k = 0; k < n_in; k++) {
        if (in_sizes[k] == N_TOK * D_DIM) feat = (const float*)d_in[k];
        else if (in_sizes[k] == N_TOK)    attn = (const float*)d_in[k];
    }
    int topk = out_size;
    if (topk > TK) topk = TK;

    const int smem_sel = (TPB * TK + TK) * (int)sizeof(float);   // 68 KB
    cudaFuncSetAttribute(select_ker, cudaFuncAttributeMaxDynamicSharedMemorySize, smem_sel);

    init_ker<<<2, 1024>>>();
    minmax_ker<<<1, 256>>>(attn);
    relev_ker<<<16, 256>>>(attn);
    norm_ker<<<N_TOK, 256>>>(feat);
    gemm_ker<<<dim3(32, 32), 256>>>();
    diag_ker<<<16, 256>>>();
    argmax0_ker<<<4, 1024>>>();
    select_ker<<<NSEL, NTHR, smem_sel>>>((float*)d_out, topk);
}

// round 16
// speedup vs baseline: 1.0425x; 1.0425x over previous
#include <cuda_runtime.h>
#include <math.h>

#define N_TOK 4096
#define D_DIM 2048
#define TK    1024
#define NSEL  256         // persistent selection CTAs (2 per SM), 16 tokens each
#define TPB   16          // tokens per CTA
#define EPSV  1e-6f

// ---------------- device global scratch (no allocations allowed) ----------------
__device__ float g_F[N_TOK][D_DIM];      // normalized features (32 MB)
__device__ float g_K[N_TOK][N_TOK];      // r_n * sim * r_m     (64 MB)
__device__ float g_C[N_TOK][TK];         // cis, token-major: g_C[m][t] = cis[t][m]
__device__ float g_r[N_TOK];
__device__ float g_di2s[N_TOK];

struct __align__(16) StepSlot {
    unsigned long long slot;   // packed (value, idx) winner key
    unsigned int done;         // CTA completion count
    unsigned int pad;
};
__device__ StepSlot g_step[TK + 2];

// ---------------- init: reset per-replay state ------------------------------------
__global__ void init_ker() {
    int t = blockIdx.x * blockDim.x + threadIdx.x;
    if (t < TK + 2) { g_step[t].slot = 0ull; g_step[t].done = 0u; g_step[t].pad = 0u; }
}

// ---------------- fused: min/max of relevance + relevance ---------------------------
// NOTE: final scaling MUST be a true division (bit-exact vs reference); a
// multiply-by-reciprocal differs in the last ulp and perturbs the greedy argmax.
__global__ void relev_ker(const float* __restrict__ attn) {
    __shared__ float smn[1024], smx[1024];
    int tid = threadIdx.x;
    float v0 = -attn[tid], v1 = -attn[tid + 1024];
    float v2 = -attn[tid + 2048], v3 = -attn[tid + 3072];
    float mn = fminf(fminf(v0, v1), fminf(v2, v3));
    float mx = fmaxf(fmaxf(v0, v1), fmaxf(v2, v3));
    smn[tid] = mn; smx[tid] = mx; __syncthreads();
    for (int s = 512; s > 0; s >>= 1) {
        if (tid < s) {
            smn[tid] = fminf(smn[tid], smn[tid + s]);
            smx[tid] = fmaxf(smx[tid], smx[tid + s]);
        }
        __syncthreads();
    }
    float gmn = smn[0], gmx = smx[0];
    float den = gmx - gmn;
    g_r[tid]        = (v0 - gmn + EPSV) / den;
    g_r[tid + 1024] = (v1 - gmn + EPSV) / den;
    g_r[tid + 2048] = (v2 - gmn + EPSV) / den;
    g_r[tid + 3072] = (v3 - gmn + EPSV) / den;
}

// ---------------- row L2-normalize --------------------------------------------------
__global__ void norm_ker(const float* __restrict__ X) {
    int row = blockIdx.x;
    int tid = threadIdx.x;
    const float4* x4 = (const float4*)(X + (size_t)row * D_DIM);
    float4 v0 = x4[tid], v1 = x4[tid + 256];
    float ss = v0.x*v0.x + v0.y*v0.y + v0.z*v0.z + v0.w*v0.w
             + v1.x*v1.x + v1.y*v1.y + v1.z*v1.z + v1.w*v1.w;
    __shared__ float sred[256];
    sred[tid] = ss; __syncthreads();
    for (int s = 128; s > 0; s >>= 1) {
        if (tid < s) sred[tid] += sred[tid + s];
        __syncthreads();
    }
    float inv = 1.0f / sqrtf(sred[0]);
    v0.x *= inv; v0.y *= inv; v0.z *= inv; v0.w *= inv;
    v1.x *= inv; v1.y *= inv; v1.z *= inv; v1.w *= inv;
    float4* o4 = (float4*)(&g_F[row][0]);
    o4[tid] = v0; o4[tid + 256] = v1;
}

// ---------------- packed f32x2 FMA helpers -----------------------------------------
__device__ __forceinline__ void fma2(unsigned long long& d,
                                     unsigned long long a, unsigned long long b) {
    asm("fma.rn.f32x2 %0, %1, %2, %3;" : "=l"(d) : "l"(a), "l"(b), "l"(d));
}
__device__ __forceinline__ unsigned long long bcast2(float x) {
    unsigned long long d;
    unsigned r = __float_as_uint(x);
    asm("mov.b64 %0, {%1, %1};" : "=l"(d) : "r"(r));
    return d;
}

// ---------------- K = diag(r)*F F^T*diag(r), symmetric half, double-buffered -------
__global__ void __launch_bounds__(256) gemm_ker() {
    int bx = blockIdx.x, by = blockIdx.y;
    if (by > bx) return;                 // lower-triangular tiles only
    __shared__ float As[2][16][132];
    __shared__ float Bs[2][16][132];
    int tid = threadIdx.x;
    int tx = tid & 15, ty = tid >> 4;
    int lr = tid >> 2;                   // 0..63
    int lc = (tid & 3) * 4;              // 0,4,8,12
    const float* Ab = &g_F[bx * 128 + lr][lc];
    const float* Bb = &g_F[by * 128 + lr][lc];
    unsigned long long acc2[8][4];       // 8 rows x 4 packed col-pairs
    #pragma unroll
    for (int i = 0; i < 8; i++)
        #pragma unroll
        for (int p = 0; p < 4; p++) acc2[i][p] = 0ull;  // (0.0f, 0.0f)

    // prologue: load chunk 0 into registers
    float4 a0 = *(const float4*)(Ab);
    float4 a1 = *(const float4*)(Ab + (size_t)64 * D_DIM);
    float4 b0 = *(const float4*)(Bb);
    float4 b1 = *(const float4*)(Bb + (size_t)64 * D_DIM);

    for (int chunk = 0; chunk < D_DIM / 16; chunk++) {
        int buf = chunk & 1;
        As[buf][lc + 0][lr] = a0.x; As[buf][lc + 1][lr] = a0.y;
        As[buf][lc + 2][lr] = a0.z; As[buf][lc + 3][lr] = a0.w;
        As[buf][lc + 0][lr + 64] = a1.x; As[buf][lc + 1][lr + 64] = a1.y;
        As[buf][lc + 2][lr + 64] = a1.z; As[buf][lc + 3][lr + 64] = a1.w;
        Bs[buf][lc + 0][lr] = b0.x; Bs[buf][lc + 1][lr] = b0.y;
        Bs[buf][lc + 2][lr] = b0.z; Bs[buf][lc + 3][lr] = b0.w;
        Bs[buf][lc + 0][lr + 64] = b1.x; Bs[buf][lc + 1][lr + 64] = b1.y;
        Bs[buf][lc + 2][lr + 64] = b1.z; Bs[buf][lc + 3][lr + 64] = b1.w;
        __syncthreads();
        // prefetch next chunk into registers (overlaps with compute below)
        if (chunk + 1 < D_DIM / 16) {
            int k0 = (chunk + 1) * 16;
            a0 = *(const float4*)(Ab + k0);
            a1 = *(const float4*)(Ab + (size_t)64 * D_DIM + k0);
            b0 = *(const float4*)(Bb + k0);
            b1 = *(const float4*)(Bb + (size_t)64 * D_DIM + k0);
        }
        #pragma unroll
        for (int kk = 0; kk < 16; kk++) {
            float4 ra0 = *(float4*)&As[buf][kk][ty * 8];
            float4 ra1 = *(float4*)&As[buf][kk][ty * 8 + 4];
            const unsigned long long* bp = (const unsigned long long*)&Bs[buf][kk][tx * 8];
            unsigned long long bb[4] = {bp[0], bp[1], bp[2], bp[3]};
            float a[8] = {ra0.x, ra0.y, ra0.z, ra0.w, ra1.x, ra1.y, ra1.z, ra1.w};
            #pragma unroll
            for (int i = 0; i < 8; i++) {
                unsigned long long aa = bcast2(a[i]);
                #pragma unroll
                for (int p = 0; p < 4; p++) fma2(acc2[i][p], aa, bb[p]);
            }
        }
        __syncthreads();
    }

    int r0 = bx * 128 + ty * 8;
    int c0 = by * 128 + tx * 8;
    float rr[8], rc[8];
    #pragma unroll
    for (int i = 0; i < 8; i++) rr[i] = g_r[r0 + i];
    #pragma unroll
    for (int j = 0; j < 8; j++) rc[j] = g_r[c0 + j];
    #pragma unroll
    for (int i = 0; i < 8; i++) {
        float av[8];
        #pragma unroll
        for (int p = 0; p < 4; p++) {
            unsigned lo, hi;
            asm("mov.b64 {%0, %1}, %2;" : "=r"(lo), "=r"(hi) : "l"(acc2[i][p]));
            av[2 * p]     = __uint_as_float(lo);
            av[2 * p + 1] = __uint_as_float(hi);
        }
        #pragma unroll
        for (int j = 0; j < 8; j++) {
            float v = av[j] * rr[i] * rc[j];
            g_K[r0 + i][c0 + j] = v;
            if (bx != by) g_K[c0 + j][r0 + i] = v;
        }
    }
}

// ---------------- key packing: order-preserving float + first-index tiebreak -------
__device__ __forceinline__ unsigned long long packkey(float f, int idx) {
    unsigned u = __float_as_uint(f);
    u = (u & 0x80000000u) ? ~u : (u | 0x80000000u);
    return ((unsigned long long)u << 32) | (unsigned)(0xFFFFFFFFu - (unsigned)idx);
}

// ---------------- fused: diag + initial argmax --------------------------------------
__global__ void diag_argmax0_ker() {
    int n = blockIdx.x * 1024 + threadIdx.x;
    int lane = threadIdx.x & 31;
    float d = g_K[n][n];
    g_di2s[n] = d;
    unsigned long long k = packkey(d, n);
    #pragma unroll
    for (int o = 16; o; o >>= 1) {
        unsigned long long t = __shfl_xor_sync(0xffffffffu, k, o);
        if (t > k) k = t;
    }
    if (lane == 0) atomicMax(&g_step[0].slot, k);
}

// ---------------- persistent greedy DPP selection (R13 config) ----------------------
// 256 CTAs x 256 threads (2 CTAs/SM); CTA b owns tokens b*16..b*16+15; warp w owns 2.
__global__ void __launch_bounds__(256, 2) select_ker(float* __restrict__ out, int topk) {
    extern __shared__ float sh[];
    float* C_sh  = sh;                    // [TPB][TK] = 64 KB, own C rows
    float* cj_sh = sh + TPB * TK;         // [TK]      = 4 KB
    __shared__ float kj_sh[TPB];
    __shared__ float di_sh[TPB];
    __shared__ unsigned long long warpmax[8];
    __shared__ unsigned long long s_key;

    int tid = threadIdx.x, lane = tid & 31, wid = tid >> 5;
    int m0 = (int)blockIdx.x * TPB;

    if (tid < TPB) di_sh[tid] = g_di2s[m0 + tid];
    __syncthreads();

    for (int i = 0; i < topk; i++) {
        // ---- wait for step-i winner; fused poll reads done+slot in one 16B load ----
        if (tid == 0) {
            if (i == 0) {
                s_key = *(volatile unsigned long long*)&g_step[0].slot;  // prior kernel
            } else {
                unsigned w0, w1, w2, w3;
                for (;;) {
                    asm volatile("ld.volatile.global.v4.u32 {%0,%1,%2,%3}, [%4];"
                                 : "=r"(w0), "=r"(w1), "=r"(w2), "=r"(w3)
                                 : "l"(&g_step[i]));
                    if (w2 >= (unsigned)NSEL) break;      // done counter
                }
                __threadfence();
                s_key = ((unsigned long long)w1 << 32) | w0;  // little-endian slot
            }
        }
        __syncthreads();

        unsigned long long key = s_key;
        int j = (int)(0xFFFFFFFFu - (unsigned)(key & 0xFFFFFFFFull));
        unsigned uv = (unsigned)(key >> 32);
        uv = (uv & 0x80000000u) ? (uv ^ 0x80000000u) : ~uv;
        float sd = sqrtf(__uint_as_float(uv));

        if (blockIdx.x == 0 && tid == 0) out[i] = (float)j;   // float32 output

        // ---- concurrent: warp0 prefetches K[j] slice; warps 1-7 stage C[j][0..i) ----
        int i4 = i >> 2;
        if (wid == 0) {
            if (lane < TPB) kj_sh[lane] = __ldcg(&g_K[j][m0 + lane]);
        } else {
            int st = tid - 32;                         // 0..223
            const float4* gcj4 = (const float4*)&g_C[j][0];
            for (int t = st; t < i4; t += 224)
                ((float4*)cj_sh)[t] = __ldcg(&gcj4[t]);
            for (int t = (i4 << 2) + st; t < i; t += 224)
                cj_sh[t] = __ldcg(&g_C[j][t]);
        }
        __syncthreads();

        // ---- 2-token interleaved dot over staged cj ----
        const float4* cj4 = (const float4*)cj_sh;
        const float4* cm0 = (const float4*)(C_sh + (wid * 2 + 0) * TK);
        const float4* cm1 = (const float4*)(C_sh + (wid * 2 + 1) * TK);
        float cd0 = 0.f, cd1 = 0.f;
        for (int t = lane; t < i4; t += 32) {
            float4 a = cj4[t];
            float4 b0 = cm0[t], b1 = cm1[t];
            cd0 += a.x * b0.x + a.y * b0.y + a.z * b0.z + a.w * b0.w;
            cd1 += a.x * b1.x + a.y * b1.y + a.z * b1.z + a.w * b1.w;
        }
        for (int t = (i4 << 2) + lane; t < i; t += 32) {
            float a = cj_sh[t];
            cd0 += a * C_sh[(wid * 2 + 0) * TK + t];
            cd1 += a * C_sh[(wid * 2 + 1) * TK + t];
        }
        #pragma unroll
        for (int o = 16; o; o >>= 1) {
            cd0 += __shfl_xor_sync(0xffffffffu, cd0, o);
            cd1 += __shfl_xor_sync(0xffffffffu, cd1, o);
        }

        unsigned long long best = 0ull;
        if (lane == 0) {
            float cds[2] = {cd0, cd1};
            #pragma unroll
            for (int mi = 0; mi < 2; mi++) {
                int ml = wid * 2 + mi;
                int m  = m0 + ml;
                float eis = (kj_sh[ml] - cds[mi]) / sd;
                C_sh[ml * TK + i] = eis;           // smem copy (own dots)
                g_C[m][i] = eis;                   // publish for other CTAs
                float dcur = di_sh[ml];
                if (dcur != -INFINITY) {
                    float d = dcur - eis * eis;
                    if (m == j) d = -INFINITY;
                    di_sh[ml] = d;
                    if (d != -INFINITY) {
                        unsigned long long k = packkey(d, m);
                        if (k > best) best = k;
                    }
                }
            }
        }

        if (i + 1 < topk) {
            if (lane == 0) warpmax[wid] = best;
            __syncthreads();
            if (wid == 0) {
                unsigned long long k = (lane < 8) ? warpmax[lane] : 0ull;
                #pragma unroll
                for (int o = 4; o; o >>= 1) {
                    unsigned long long t = __shfl_xor_sync(0xffffffffu, k, o);
                    if (t > k) k = t;
                }
                if (lane == 0 && k) atomicMax(&g_step[i + 1].slot, k);
            }
            // ---- publish: make C writes + slot contribution visible, then signal ----
            __threadfence();
            __syncthreads();
            if (tid == 0) atomicAdd(&g_step[i + 1].done, 1u);
        }
    }
}

// ---------------- host entry --------------------------------------------------------
extern "C" void kernel_launch(void* const* d_in, const int* in_sizes, int n_in,
                              void* d_out, int out_size) {
    // Robust input selection by element count
    const float* feat = (const float*)d_in[0];
    const float* attn = (const float*)d_in[1];
    for (int k = 0; k < n_in; k++) {
        if (in_sizes[k] == N_TOK * D_DIM) feat = (const float*)d_in[k];
        else if (in_sizes[k] == N_TOK)    attn = (const float*)d_in[k];
    }
    int topk = out_size;
    if (topk > TK) topk = TK;

    const int smem_sel = (TPB * TK + TK) * (int)sizeof(float);   // 68 KB
    cudaFuncSetAttribute(select_ker, cudaFuncAttributeMaxDynamicSharedMemorySize, smem_sel);

    init_ker<<<2, 1024>>>();
    relev_ker<<<1, 1024>>>(attn);
    norm_ker<<<N_TOK, 256>>>(feat);
    gemm_ker<<<dim3(32, 32), 256>>>();
    diag_argmax0_ker<<<4, 1024>>>();
    select_ker<<<NSEL, 256, smem_sel>>>((float*)d_out, topk);
}